// round 1
// baseline (speedup 1.0000x reference)
#include <cuda_runtime.h>
#include <cuda_bf16.h>
#include <math.h>

// SpikeMLP: 3x (Linear -> BN(inference) -> LIF) over T=16 timesteps.
// Shapes: B=128, Din=1024, H=2048, Dout=1024, T=16.
// Strategy (round 1, fp32 baseline):
//   - transpose spikes [B,Din,T] -> [B*T, Din]
//   - GEMM  X[m,o] = sum_i S[m,i]*W[o,i]   (fp32 SIMT tiled)
//   - LIF kernel: per-(b,o) scan over 16 timesteps with BN folded in
//     (op order matches reference: (gemm + b - mm) * g / sqrt(mv+eps) + be)
//   - final layer averages spikes -> out [B, Dout]

#define B_SZ   128
#define T_SZ   16
#define DIN    1024
#define HID    2048
#define DOUT   1024
#define M_SZ   (B_SZ * T_SZ)   // 2048

// Scratch (device globals; allocation inside kernel_launch is forbidden)
__device__ float g_S0[M_SZ * DIN];   // 8 MB   transposed input spikes
__device__ float g_X [M_SZ * HID];   // 16 MB  GEMM output (reused per layer)
__device__ float g_S1[M_SZ * HID];   // 16 MB  layer-0 spikes
__device__ float g_S2[M_SZ * HID];   // 16 MB  layer-1 spikes

// ---------------------------------------------------------------------------
// Transpose [B, K, T] -> [B*T, K]
// ---------------------------------------------------------------------------
__global__ void transpose_spk_kernel(const float* __restrict__ in,
                                     float* __restrict__ out, int K)
{
    int idx = blockIdx.x * blockDim.x + threadIdx.x;
    int total = B_SZ * T_SZ * K;
    if (idx >= total) return;
    int i  = idx % K;
    int bt = idx / K;
    int b  = bt >> 4;        // /16
    int t  = bt & 15;
    out[idx] = in[((size_t)b * K + i) * T_SZ + t];
}

// ---------------------------------------------------------------------------
// fp32 tiled GEMM:  C[M,N] = A[M,K] * B[N,K]^T
// A row-major (K contiguous), B row-major (K contiguous) -> both K-fastest.
// BM=BN=128, BK=16, 256 threads, 8x8 microtile.
// M,N multiples of 128; K multiple of 16 (guaranteed by problem shapes).
// ---------------------------------------------------------------------------
#define BM 128
#define BN 128
#define BK 16
#define TM 8
#define TN 8

__global__ __launch_bounds__(256, 2)
void gemm_nt_kernel(const float* __restrict__ A,
                    const float* __restrict__ Bm,
                    float* __restrict__ C,
                    int M, int N, int K)
{
    __shared__ float As[BK][BM + 4];
    __shared__ float Bs[BK][BN + 4];

    const int tid = threadIdx.x;
    const int tx  = tid & 15;          // 0..15 -> column group
    const int ty  = tid >> 4;          // 0..15 -> row group

    const int rowBase = blockIdx.y * BM;
    const int colBase = blockIdx.x * BN;

    float acc[TM][TN];
    #pragma unroll
    for (int i = 0; i < TM; i++)
        #pragma unroll
        for (int j = 0; j < TN; j++)
            acc[i][j] = 0.0f;

    // Each K-slab: 128 rows x 16 k = 512 float4 per tile; 256 threads -> 2 each.
    for (int kk = 0; kk < K; kk += BK) {
        #pragma unroll
        for (int l = 0; l < 2; l++) {
            int vecId = tid + l * 256;       // 0..511
            int r     = vecId >> 2;          // 0..127
            int kv    = vecId & 3;           // float4 index within 16-k row

            float4 av = *reinterpret_cast<const float4*>(
                A + (size_t)(rowBase + r) * K + kk + kv * 4);
            As[kv * 4 + 0][r] = av.x;
            As[kv * 4 + 1][r] = av.y;
            As[kv * 4 + 2][r] = av.z;
            As[kv * 4 + 3][r] = av.w;

            float4 bv = *reinterpret_cast<const float4*>(
                Bm + (size_t)(colBase + r) * K + kk + kv * 4);
            Bs[kv * 4 + 0][r] = bv.x;
            Bs[kv * 4 + 1][r] = bv.y;
            Bs[kv * 4 + 2][r] = bv.z;
            Bs[kv * 4 + 3][r] = bv.w;
        }
        __syncthreads();

        #pragma unroll
        for (int k = 0; k < BK; k++) {
            float a[TM], b[TN];
            #pragma unroll
            for (int i = 0; i < TM; i++) a[i] = As[k][ty * TM + i];
            #pragma unroll
            for (int j = 0; j < TN; j++) b[j] = Bs[k][tx * TN + j];
            #pragma unroll
            for (int i = 0; i < TM; i++)
                #pragma unroll
                for (int j = 0; j < TN; j++)
                    acc[i][j] = fmaf(a[i], b[j], acc[i][j]);
        }
        __syncthreads();
    }

    #pragma unroll
    for (int i = 0; i < TM; i++) {
        float* crow = C + (size_t)(rowBase + ty * TM + i) * N + colBase + tx * TN;
        #pragma unroll
        for (int j = 0; j < TN; j += 4) {
            float4 v = make_float4(acc[i][j], acc[i][j+1], acc[i][j+2], acc[i][j+3]);
            *reinterpret_cast<float4*>(crow + j) = v;
        }
    }
}

// ---------------------------------------------------------------------------
// LIF over T=16 steps with BN(inference). One thread per (b, o).
// X layout: [B*T, O] with m = b*16 + t.
// Writes spikes (0/1 float) to S in the same layout.
// ---------------------------------------------------------------------------
__global__ void lif_kernel(const float* __restrict__ X,
                           const float* __restrict__ bias,
                           const float* __restrict__ g,
                           const float* __restrict__ be,
                           const float* __restrict__ mm,
                           const float* __restrict__ mv,
                           float* __restrict__ S, int O)
{
    int idx = blockIdx.x * blockDim.x + threadIdx.x;
    if (idx >= B_SZ * O) return;
    int o = idx % O;
    int b = idx / O;

    const float bi  = bias[o];
    const float gg  = g[o];
    const float bb  = be[o];
    const float m0  = mm[o];
    const float inv = 1.0f / sqrtf(mv[o] + 1e-5f);

    const float* xp  = X + (size_t)b * T_SZ * O + o;
    float*       spp = S + (size_t)b * T_SZ * O + o;

    float volt = 0.0f, sp = 0.0f;
    #pragma unroll
    for (int t = 0; t < T_SZ; t++) {
        float x  = xp[(size_t)t * O] + bi;
        float xn = gg * (x - m0) * inv + bb;
        volt = volt * (1.0f - sp) * 0.75f + xn;
        sp   = (volt > 0.5f) ? 1.0f : 0.0f;
        spp[(size_t)t * O] = sp;
    }
}

// Final layer: LIF + average spikes over T -> out[b, o]
__global__ void lif_final_kernel(const float* __restrict__ X,
                                 const float* __restrict__ bias,
                                 const float* __restrict__ g,
                                 const float* __restrict__ be,
                                 const float* __restrict__ mm,
                                 const float* __restrict__ mv,
                                 float* __restrict__ out, int O)
{
    int idx = blockIdx.x * blockDim.x + threadIdx.x;
    if (idx >= B_SZ * O) return;
    int o = idx % O;
    int b = idx / O;

    const float bi  = bias[o];
    const float gg  = g[o];
    const float bb  = be[o];
    const float m0  = mm[o];
    const float inv = 1.0f / sqrtf(mv[o] + 1e-5f);

    const float* xp = X + (size_t)b * T_SZ * O + o;

    float volt = 0.0f, sp = 0.0f, cnt = 0.0f;
    #pragma unroll
    for (int t = 0; t < T_SZ; t++) {
        float x  = xp[(size_t)t * O] + bi;
        float xn = gg * (x - m0) * inv + bb;
        volt = volt * (1.0f - sp) * 0.75f + xn;
        sp   = (volt > 0.5f) ? 1.0f : 0.0f;
        cnt += sp;
    }
    out[idx] = cnt * 0.0625f;   // /16 exact
}

// ---------------------------------------------------------------------------
// Launch
// ---------------------------------------------------------------------------
extern "C" void kernel_launch(void* const* d_in, const int* in_sizes, int n_in,
                              void* d_out, int out_size)
{
    const float* spk = (const float*)d_in[0];
    const float* W0  = (const float*)d_in[1];
    const float* b0  = (const float*)d_in[2];
    const float* g0  = (const float*)d_in[3];
    const float* be0 = (const float*)d_in[4];
    const float* mm0 = (const float*)d_in[5];
    const float* mv0 = (const float*)d_in[6];
    const float* W1  = (const float*)d_in[7];
    const float* b1  = (const float*)d_in[8];
    const float* g1  = (const float*)d_in[9];
    const float* be1 = (const float*)d_in[10];
    const float* mm1 = (const float*)d_in[11];
    const float* mv1 = (const float*)d_in[12];
    const float* Wo  = (const float*)d_in[13];
    const float* bo  = (const float*)d_in[14];
    const float* go  = (const float*)d_in[15];
    const float* beo = (const float*)d_in[16];
    const float* mmo = (const float*)d_in[17];
    const float* mvo = (const float*)d_in[18];

    float* out = (float*)d_out;

    float *S0, *X, *S1, *S2;
    cudaGetSymbolAddress((void**)&S0, g_S0);
    cudaGetSymbolAddress((void**)&X,  g_X);
    cudaGetSymbolAddress((void**)&S1, g_S1);
    cudaGetSymbolAddress((void**)&S2, g_S2);

    // 1) transpose input spikes -> [M, Din]
    {
        int total = M_SZ * DIN;
        transpose_spk_kernel<<<(total + 255) / 256, 256>>>(spk, S0, DIN);
    }

    // 2) layer 0: GEMM [M,DIN]x[HID,DIN]^T -> X[M,HID]; LIF -> S1
    {
        dim3 grid(HID / BN, M_SZ / BM);
        gemm_nt_kernel<<<grid, 256>>>(S0, W0, X, M_SZ, HID, DIN);
        int total = B_SZ * HID;
        lif_kernel<<<(total + 255) / 256, 256>>>(X, b0, g0, be0, mm0, mv0, S1, HID);
    }

    // 3) layer 1: GEMM [M,HID]x[HID,HID]^T -> X; LIF -> S2
    {
        dim3 grid(HID / BN, M_SZ / BM);
        gemm_nt_kernel<<<grid, 256>>>(S1, W1, X, M_SZ, HID, HID);
        int total = B_SZ * HID;
        lif_kernel<<<(total + 255) / 256, 256>>>(X, b1, g1, be1, mm1, mv1, S2, HID);
    }

    // 4) output layer: GEMM [M,HID]x[DOUT,HID]^T -> X; LIF + time-average -> out
    {
        dim3 grid(DOUT / BN, M_SZ / BM);
        gemm_nt_kernel<<<grid, 256>>>(S2, Wo, X, M_SZ, DOUT, HID);
        int total = B_SZ * DOUT;
        lif_final_kernel<<<(total + 255) / 256, 256>>>(X, bo, go, beo, mmo, mvo, out, DOUT);
    }
}

// round 8
// speedup vs baseline: 1.0489x; 1.0489x over previous
#include <cuda_runtime.h>
#include <math.h>
#include <stdint.h>

// SpikeMLP: 3x (Linear -> BN -> LIF), B=128, Din=1024, H=2048, Dout=1024, T=16.
// Round 8 (= round 7 resubmit; broker timeout): EXACT fp32-GEMM emulation via
// int8 tensor cores (IMMA).
//   m = round(w * 2^27), |m| <= 2^22, per-weight error <= 2^-28.
//   m = d2*65536 + d1*256 + d0, balanced signed digits d_i in [-128,128).
//   X = 2^-27 * (65536*S2 + 256*S1 + S0), S_p = sum spikes*d_p  (exact int32).
//   One GEMM over K'=3K with Horner acc*=256 at plane boundaries (d2,d1,d0).
// Integer accumulation has ZERO rounding -> only error is the weight
// quantization (2^-28/weight), far below what the passing fp32 baseline had.

#define B_SZ   128
#define T_SZ   16
#define DIN    1024
#define HID    2048
#define DOUT   1024
#define M_SZ   (B_SZ * T_SZ)   // 2048

#define W_SCALE     134217728.0f            // 2^27
#define W_INV_SCALE 7.450580596923828e-9f   // 2^-27 (exact)

// ------------------------- scratch (device globals) -------------------------
__device__ __align__(256) int8_t g_S0[M_SZ * 3 * DIN];   // 6 MB  spikes x3 planes
__device__ __align__(256) int8_t g_S1[M_SZ * 3 * HID];   // 12 MB
__device__ __align__(256) int8_t g_S2[M_SZ * 3 * HID];   // 12 MB
__device__ __align__(256) float  g_X [M_SZ * HID];       // 16 MB GEMM out (fp32)
__device__ __align__(256) int8_t g_W0d[HID  * 3 * DIN];  // 6 MB  [d2|d1|d0]
__device__ __align__(256) int8_t g_W1d[HID  * 3 * HID];  // 12 MB
__device__ __align__(256) int8_t g_Wod[DOUT * 3 * HID];  // 6 MB

// ------------------------- PTX helpers --------------------------------------
__device__ __forceinline__ void cpasync16(uint32_t dst, const void* src) {
    asm volatile("cp.async.cg.shared.global [%0], [%1], 16;\n" :: "r"(dst), "l"(src));
}
__device__ __forceinline__ void cp_commit() { asm volatile("cp.async.commit_group;\n"); }
__device__ __forceinline__ void cp_wait1()  { asm volatile("cp.async.wait_group 1;\n"); }
__device__ __forceinline__ void cp_wait0()  { asm volatile("cp.async.wait_group 0;\n"); }

__device__ __forceinline__ void ldsm4(uint32_t& r0, uint32_t& r1, uint32_t& r2,
                                      uint32_t& r3, uint32_t addr) {
    asm volatile("ldmatrix.sync.aligned.m8n8.x4.shared.b16 {%0,%1,%2,%3}, [%4];\n"
                 : "=r"(r0), "=r"(r1), "=r"(r2), "=r"(r3) : "r"(addr));
}
__device__ __forceinline__ void mma16832s8(int* c, const uint32_t* a, const uint32_t* b) {
    asm volatile(
        "mma.sync.aligned.m16n8k32.row.col.s32.s8.s8.s32 "
        "{%0,%1,%2,%3}, {%4,%5,%6,%7}, {%8,%9}, {%0,%1,%2,%3};\n"
        : "+r"(c[0]), "+r"(c[1]), "+r"(c[2]), "+r"(c[3])
        : "r"(a[0]), "r"(a[1]), "r"(a[2]), "r"(a[3]), "r"(b[0]), "r"(b[1]));
}

// ------------------------- weight digit split --------------------------------
// W fp32 [N][K] -> P s8 [N][3K] = [d2 plane | d1 plane | d0 plane]
__device__ __forceinline__ void split3(float w, int8_t& d2, int8_t& d1, int8_t& d0)
{
    int m  = __float2int_rn(w * W_SCALE);          // |m| <= 2^22
    int e0 = ((m + 128) & 255) - 128;              // m mod± 256
    int m1 = (m - e0) >> 8;                        // exact
    int e1 = ((m1 + 128) & 255) - 128;
    int e2 = (m1 - e1) >> 8;                       // in [-64, 64]
    d0 = (int8_t)e0; d1 = (int8_t)e1; d2 = (int8_t)e2;
}

__global__ void split_w_kernel(const float* __restrict__ W, int8_t* __restrict__ P,
                               int N, int K)
{
    int idx = blockIdx.x * blockDim.x + threadIdx.x;   // over N*K/4
    int total = N * (K >> 2);
    if (idx >= total) return;
    int n  = idx / (K >> 2);
    int k4 = (idx - n * (K >> 2)) * 4;
    float4 w = *reinterpret_cast<const float4*>(&W[(size_t)n * K + k4]);
    char4 c2, c1, c0;
    split3(w.x, (int8_t&)c2.x, (int8_t&)c1.x, (int8_t&)c0.x);
    split3(w.y, (int8_t&)c2.y, (int8_t&)c1.y, (int8_t&)c0.y);
    split3(w.z, (int8_t&)c2.z, (int8_t&)c1.z, (int8_t&)c0.z);
    split3(w.w, (int8_t&)c2.w, (int8_t&)c1.w, (int8_t&)c0.w);
    size_t base = (size_t)n * 3 * K;
    *reinterpret_cast<char4*>(&P[base + k4])         = c2;
    *reinterpret_cast<char4*>(&P[base + K + k4])     = c1;
    *reinterpret_cast<char4*>(&P[base + 2 * K + k4]) = c0;
}

// ------------------------- input transpose -----------------------------------
// in [B, K, T] fp32 -> out s8 [M][3K]: spike replicated into all 3 planes
__global__ void transpose_spk_kernel(const float* __restrict__ in,
                                     int8_t* __restrict__ out, int K)
{
    int idx = blockIdx.x * blockDim.x + threadIdx.x;
    int total = M_SZ * K;
    if (idx >= total) return;
    int i  = idx % K;
    int bt = idx / K;
    int b  = bt >> 4;
    int t  = bt & 15;
    float s = in[((size_t)b * K + i) * T_SZ + t];
    int8_t v = (s > 0.5f) ? 1 : 0;
    size_t row = (size_t)bt * 3 * K;
    out[row + i]         = v;
    out[row + K + i]     = v;
    out[row + 2 * K + i] = v;
}

// ------------------------- s8 tensor GEMM (exact) ----------------------------
// C[M][N] = 2^-27 * (A_spk[M][3K] x Wd[N][3K]^T with Horner plane combine)
// BM=BN=128, 64-byte k-tiles, 256 threads, 8 warps (4M x 2N), warp tile 32x64.
#define BM   128
#define BN   128
#define BKB  64    // bytes per k-tile
#define STRB 80    // bytes per smem row (64 + 16 pad -> conflict-free ldmatrix)

__global__ __launch_bounds__(256)
void igemm_nt_kernel(const int8_t* __restrict__ A, const int8_t* __restrict__ Bp,
                     float* __restrict__ C, int M, int N, int K3)
{
    __shared__ __align__(128) int8_t sA[2][BM * STRB];
    __shared__ __align__(128) int8_t sB[2][BN * STRB];

    const int tid  = threadIdx.x;
    const int warp = tid >> 5;
    const int lane = tid & 31;
    const int rowBase = blockIdx.y * BM;
    const int colBase = blockIdx.x * BN;
    const int warpM = (warp >> 1) * 32;
    const int warpN = (warp & 1) * 64;

    int acc[2][8][4];
    #pragma unroll
    for (int mi = 0; mi < 2; mi++)
        #pragma unroll
        for (int nj = 0; nj < 8; nj++)
            #pragma unroll
            for (int q = 0; q < 4; q++)
                acc[mi][nj][q] = 0;

    const int ldRow   = tid >> 2;   // 0..63
    const int ldChunk = tid & 3;    // 0..3 (16B chunks of the 64B row-slab)

    const int nT    = K3 / BKB;     // multiple of 3 (K mult of 64)
    const int third = nT / 3;

    // ---- prologue: tile 0 -> buf 0
    {
        #pragma unroll
        for (int h = 0; h < 2; h++) {
            int row = ldRow + h * 64;
            const int8_t* gA = A + (size_t)(rowBase + row) * K3 + ldChunk * 16;
            cpasync16((uint32_t)__cvta_generic_to_shared(&sA[0][row * STRB + ldChunk * 16]), gA);
            const int8_t* gB = Bp + (size_t)(colBase + row) * K3 + ldChunk * 16;
            cpasync16((uint32_t)__cvta_generic_to_shared(&sB[0][row * STRB + ldChunk * 16]), gB);
        }
        cp_commit();
    }

    int buf = 0;
    for (int t = 0; t < nT; t++) {
        if (t + 1 < nT) {
            int kk = (t + 1) * BKB;
            #pragma unroll
            for (int h = 0; h < 2; h++) {
                int row = ldRow + h * 64;
                const int8_t* gA = A + (size_t)(rowBase + row) * K3 + kk + ldChunk * 16;
                cpasync16((uint32_t)__cvta_generic_to_shared(&sA[buf ^ 1][row * STRB + ldChunk * 16]), gA);
                const int8_t* gB = Bp + (size_t)(colBase + row) * K3 + kk + ldChunk * 16;
                cpasync16((uint32_t)__cvta_generic_to_shared(&sB[buf ^ 1][row * STRB + ldChunk * 16]), gB);
            }
            cp_commit();
            cp_wait1();
        } else {
            cp_wait0();
        }
        __syncthreads();

        // ---- 2 mma k-steps of 32 bytes each
        #pragma unroll
        for (int ks = 0; ks < 2; ks++) {
            uint32_t aF[2][4];
            uint32_t bF[8][2];
            #pragma unroll
            for (int mi = 0; mi < 2; mi++) {
                int row   = warpM + mi * 16 + (lane & 15);
                int colB  = ks * 32 + (lane >> 4) * 16;     // byte offset
                uint32_t addr = (uint32_t)__cvta_generic_to_shared(&sA[buf][row * STRB + colB]);
                ldsm4(aF[mi][0], aF[mi][1], aF[mi][2], aF[mi][3], addr);
            }
            #pragma unroll
            for (int nq = 0; nq < 4; nq++) {
                int row  = warpN + nq * 16 + (lane & 15);
                int colB = ks * 32 + (lane >> 4) * 16;
                uint32_t addr = (uint32_t)__cvta_generic_to_shared(&sB[buf][row * STRB + colB]);
                uint32_t r0, r1, r2, r3;
                ldsm4(r0, r1, r2, r3, addr);
                bF[2 * nq][0]     = r0; bF[2 * nq][1]     = r2;
                bF[2 * nq + 1][0] = r1; bF[2 * nq + 1][1] = r3;
            }
            #pragma unroll
            for (int mi = 0; mi < 2; mi++)
                #pragma unroll
                for (int nj = 0; nj < 8; nj++)
                    mma16832s8(acc[mi][nj], aF[mi], bF[nj]);
        }
        __syncthreads();
        buf ^= 1;

        // ---- Horner: finished a digit plane -> scale accumulators by 256
        if (t + 1 == third || t + 1 == 2 * third) {
            #pragma unroll
            for (int mi = 0; mi < 2; mi++)
                #pragma unroll
                for (int nj = 0; nj < 8; nj++)
                    #pragma unroll
                    for (int q = 0; q < 4; q++)
                        acc[mi][nj][q] <<= 8;
        }
    }

    // ---- epilogue: exact int -> fp32 (single RN rounding)
    #pragma unroll
    for (int mi = 0; mi < 2; mi++) {
        #pragma unroll
        for (int nj = 0; nj < 8; nj++) {
            int r0 = rowBase + warpM + mi * 16 + (lane >> 2);
            int c0 = colBase + warpN + nj * 8 + (lane & 3) * 2;
            float2 v0 = make_float2((float)acc[mi][nj][0] * W_INV_SCALE,
                                    (float)acc[mi][nj][1] * W_INV_SCALE);
            float2 v1 = make_float2((float)acc[mi][nj][2] * W_INV_SCALE,
                                    (float)acc[mi][nj][3] * W_INV_SCALE);
            *reinterpret_cast<float2*>(&C[(size_t)r0 * N + c0])       = v0;
            *reinterpret_cast<float2*>(&C[(size_t)(r0 + 8) * N + c0]) = v1;
        }
    }
}

// ------------------------- LIF kernels ---------------------------------------
// X fp32 [M][O] -> spikes s8 [M][3O] (replicated planes)
__global__ void lif_kernel(const float* __restrict__ X,
                           const float* __restrict__ bias,
                           const float* __restrict__ g,
                           const float* __restrict__ be,
                           const float* __restrict__ mm,
                           const float* __restrict__ mv,
                           int8_t* __restrict__ S, int O)
{
    int idx = blockIdx.x * blockDim.x + threadIdx.x;
    if (idx >= B_SZ * O) return;
    int o = idx % O;
    int b = idx / O;

    const float bi  = bias[o];
    const float gg  = g[o];
    const float bb  = be[o];
    const float m0  = mm[o];
    const float inv = 1.0f / sqrtf(mv[o] + 1e-5f);

    const float* xp = X + (size_t)b * T_SZ * O + o;
    int8_t* spp     = S + (size_t)b * T_SZ * 3 * O + o;

    float volt = 0.0f, sp = 0.0f;
    #pragma unroll
    for (int t = 0; t < T_SZ; t++) {
        float x  = xp[(size_t)t * O] + bi;
        float xn = gg * (x - m0) * inv + bb;
        volt = volt * (1.0f - sp) * 0.75f + xn;
        sp   = (volt > 0.5f) ? 1.0f : 0.0f;
        int8_t v = (volt > 0.5f) ? 1 : 0;
        spp[(size_t)t * 3 * O]         = v;
        spp[(size_t)t * 3 * O + O]     = v;
        spp[(size_t)t * 3 * O + 2 * O] = v;
    }
}

__global__ void lif_final_kernel(const float* __restrict__ X,
                                 const float* __restrict__ bias,
                                 const float* __restrict__ g,
                                 const float* __restrict__ be,
                                 const float* __restrict__ mm,
                                 const float* __restrict__ mv,
                                 float* __restrict__ out, int O)
{
    int idx = blockIdx.x * blockDim.x + threadIdx.x;
    if (idx >= B_SZ * O) return;
    int o = idx % O;
    int b = idx / O;

    const float bi  = bias[o];
    const float gg  = g[o];
    const float bb  = be[o];
    const float m0  = mm[o];
    const float inv = 1.0f / sqrtf(mv[o] + 1e-5f);

    const float* xp = X + (size_t)b * T_SZ * O + o;

    float volt = 0.0f, sp = 0.0f, cnt = 0.0f;
    #pragma unroll
    for (int t = 0; t < T_SZ; t++) {
        float x  = xp[(size_t)t * O] + bi;
        float xn = gg * (x - m0) * inv + bb;
        volt = volt * (1.0f - sp) * 0.75f + xn;
        sp   = (volt > 0.5f) ? 1.0f : 0.0f;
        cnt += sp;
    }
    out[idx] = cnt * 0.0625f;
}

// ------------------------- launch --------------------------------------------
extern "C" void kernel_launch(void* const* d_in, const int* in_sizes, int n_in,
                              void* d_out, int out_size)
{
    const float* spk = (const float*)d_in[0];
    const float* W0  = (const float*)d_in[1];
    const float* b0  = (const float*)d_in[2];
    const float* g0  = (const float*)d_in[3];
    const float* be0 = (const float*)d_in[4];
    const float* mm0 = (const float*)d_in[5];
    const float* mv0 = (const float*)d_in[6];
    const float* W1  = (const float*)d_in[7];
    const float* b1  = (const float*)d_in[8];
    const float* g1  = (const float*)d_in[9];
    const float* be1 = (const float*)d_in[10];
    const float* mm1 = (const float*)d_in[11];
    const float* mv1 = (const float*)d_in[12];
    const float* Wo  = (const float*)d_in[13];
    const float* bo  = (const float*)d_in[14];
    const float* go  = (const float*)d_in[15];
    const float* beo = (const float*)d_in[16];
    const float* mmo = (const float*)d_in[17];
    const float* mvo = (const float*)d_in[18];

    float* out = (float*)d_out;

    int8_t *S0, *S1, *S2, *W0d, *W1d, *Wod;
    float* X;
    cudaGetSymbolAddress((void**)&S0,  g_S0);
    cudaGetSymbolAddress((void**)&S1,  g_S1);
    cudaGetSymbolAddress((void**)&S2,  g_S2);
    cudaGetSymbolAddress((void**)&X,   g_X);
    cudaGetSymbolAddress((void**)&W0d, g_W0d);
    cudaGetSymbolAddress((void**)&W1d, g_W1d);
    cudaGetSymbolAddress((void**)&Wod, g_Wod);

    // weight digit splits
    split_w_kernel<<<(HID * DIN / 4 + 255) / 256, 256>>>(W0, W0d, HID, DIN);
    split_w_kernel<<<(HID * HID / 4 + 255) / 256, 256>>>(W1, W1d, HID, HID);
    split_w_kernel<<<(DOUT * HID / 4 + 255) / 256, 256>>>(Wo, Wod, DOUT, HID);

    // input transpose -> S0 [M][3*DIN]
    transpose_spk_kernel<<<(M_SZ * DIN + 255) / 256, 256>>>(spk, S0, DIN);

    // layer 0
    {
        dim3 grid(HID / BN, M_SZ / BM);
        igemm_nt_kernel<<<grid, 256>>>(S0, W0d, X, M_SZ, HID, 3 * DIN);
        lif_kernel<<<(B_SZ * HID + 255) / 256, 256>>>(X, b0, g0, be0, mm0, mv0, S1, HID);
    }
    // layer 1
    {
        dim3 grid(HID / BN, M_SZ / BM);
        igemm_nt_kernel<<<grid, 256>>>(S1, W1d, X, M_SZ, HID, 3 * HID);
        lif_kernel<<<(B_SZ * HID + 255) / 256, 256>>>(X, b1, g1, be1, mm1, mv1, S2, HID);
    }
    // output layer
    {
        dim3 grid(DOUT / BN, M_SZ / BM);
        igemm_nt_kernel<<<grid, 256>>>(S2, Wod, X, M_SZ, DOUT, 3 * HID);
        lif_final_kernel<<<(B_SZ * DOUT + 255) / 256, 256>>>(X, bo, go, beo, mmo, mvo, out, DOUT);
    }
}